// round 1
// baseline (speedup 1.0000x reference)
#include <cuda_runtime.h>
#include <math.h>

#define S_LEN   2048
#define NBATCH  64
#define DIN     512
#define HID     512
#define KTOT    1024          // DIN + HID (fused [x;h] GEMM)
#define NBLK    128
#define NTHR    256
#define HPB     4             // hidden units per block
#define NROWS   16            // 4 gates * HPB
#define KC      128           // K chunk streamed through smem
#define NCHUNK  (KTOT / KC)   // 8

// smem layout (floats):
//   Ws    [KTOT][NROWS]      = 16384   (64 KB)  persistent fused weights, k-major
//   in_s  [KC][NBATCH]       =  8192   (32 KB)  streamed [x;h] chunk, k-major
//   part  [4][NROWS][NBATCH] =  4096   (16 KB)  k-split partial gate sums
//   bias  [NROWS]            (padded to 32)
#define OFF_WS    0
#define OFF_IN    16384
#define OFF_PART  (16384 + 8192)
#define OFF_BIAS  (16384 + 8192 + 4096)
#define SMEM_FLOATS (OFF_BIAS + 32)
#define SMEM_BYTES  (SMEM_FLOATS * 4)

__device__ unsigned int g_bar;

__global__ void reset_bar_kernel() { g_bar = 0u; }

__global__ void __launch_bounds__(NTHR, 1)
lstm_persistent_kernel(const float* __restrict__ x,
                       const float* __restrict__ Wih,
                       const float* __restrict__ Whh,
                       const float* __restrict__ bih,
                       const float* __restrict__ bhh,
                       float* __restrict__ out)
{
    extern __shared__ float sm[];
    float* Ws   = sm + OFF_WS;
    float* in_s = sm + OFF_IN;
    float* part = sm + OFF_PART;
    float* bias = sm + OFF_BIAS;

    const int t  = threadIdx.x;
    const int bk = blockIdx.x;

    // ---- Load fused weight slice, k-major: Ws[k][r], r = gate*4 + jj ----
    for (int idx = t; idx < NROWS * KTOT; idx += NTHR) {
        int r = idx >> 10;            // idx / KTOT
        int k = idx & (KTOT - 1);
        int R = ((r >> 2) * HID) + bk * HPB + (r & 3);   // global gate row
        float w = (k < DIN) ? Wih[(size_t)R * DIN + k]
                            : Whh[(size_t)R * HID + (k - DIN)];
        Ws[k * NROWS + r] = w;
    }
    if (t < NROWS) {
        int r = t;
        int R = ((r >> 2) * HID) + bk * HPB + (r & 3);
        bias[r] = bih[R] + bhh[R];
    }

    // ---- thread role decode ----
    // GEMM: kq = K-quarter (within chunk), r4 = gate (row-quad), b4 = batch-quad
    const int kq = t >> 6;
    const int r4 = (t >> 4) & 3;
    const int b4 = t & 15;
    // elementwise: eb = batch, ejj = local hidden unit
    const int eb  = t & 63;
    const int ejj = t >> 6;
    // loader: lb = batch row, lkg = k sub-slice within chunk
    const int lb  = t & 63;
    const int lkg = t >> 6;

    float c_reg = 0.0f;   // persistent cell state for (eb, ejj)

    float* h_out = out;
    float* c_out = out + (size_t)S_LEN * NBATCH * HID;

    __syncthreads();

    float4 rld[8];

    for (int s = 0; s < S_LEN; ++s) {
        const float* xrow = x + ((size_t)s * NBATCH + lb) * DIN;
        const float* hrow = (s > 0) ? (h_out + ((size_t)(s - 1) * NBATCH + lb) * HID)
                                    : (const float*)0;

        // prefetch chunk 0 (always x region)
        {
            int k0 = lkg * 32;
            #pragma unroll
            for (int i = 0; i < 8; ++i)
                rld[i] = *(const float4*)(xrow + k0 + i * 4);
        }

        float acc[4][4];
        #pragma unroll
        for (int ri = 0; ri < 4; ++ri)
            #pragma unroll
            for (int bi = 0; bi < 4; ++bi)
                acc[ri][bi] = 0.0f;

        for (int c = 0; c < NCHUNK; ++c) {
            // store prefetched chunk to smem (k-major, batch contiguous)
            {
                int klb = lkg * 32;
                #pragma unroll
                for (int i = 0; i < 8; ++i) {
                    float4 v = rld[i];
                    int kl = klb + i * 4;
                    in_s[(kl + 0) * NBATCH + lb] = v.x;
                    in_s[(kl + 1) * NBATCH + lb] = v.y;
                    in_s[(kl + 2) * NBATCH + lb] = v.z;
                    in_s[(kl + 3) * NBATCH + lb] = v.w;
                }
            }
            __syncthreads();

            // prefetch next chunk (overlaps with compute below)
            if (c + 1 < NCHUNK) {
                int kg = (c + 1) * KC + lkg * 32;   // global k
                if (kg < DIN) {
                    #pragma unroll
                    for (int i = 0; i < 8; ++i)
                        rld[i] = *(const float4*)(xrow + kg + i * 4);
                } else if (s > 0) {
                    #pragma unroll
                    for (int i = 0; i < 8; ++i)
                        rld[i] = *(const float4*)(hrow + (kg - DIN) + i * 4);
                } else {
                    #pragma unroll
                    for (int i = 0; i < 8; ++i)
                        rld[i] = make_float4(0.f, 0.f, 0.f, 0.f);
                }
            }

            // compute this chunk: each thread covers its 32-wide k slice
            const float* WsC = Ws + (c * KC) * NROWS;
            const int klo = kq * 32;
            #pragma unroll
            for (int kl = 0; kl < 32; ++kl) {
                int k = klo + kl;
                float4 iv = *(const float4*)(in_s + k * NBATCH + (b4 << 2));
                float4 wv = *(const float4*)(WsC + k * NROWS + (r4 << 2));
                acc[0][0] = fmaf(wv.x, iv.x, acc[0][0]);
                acc[0][1] = fmaf(wv.x, iv.y, acc[0][1]);
                acc[0][2] = fmaf(wv.x, iv.z, acc[0][2]);
                acc[0][3] = fmaf(wv.x, iv.w, acc[0][3]);
                acc[1][0] = fmaf(wv.y, iv.x, acc[1][0]);
                acc[1][1] = fmaf(wv.y, iv.y, acc[1][1]);
                acc[1][2] = fmaf(wv.y, iv.z, acc[1][2]);
                acc[1][3] = fmaf(wv.y, iv.w, acc[1][3]);
                acc[2][0] = fmaf(wv.z, iv.x, acc[2][0]);
                acc[2][1] = fmaf(wv.z, iv.y, acc[2][1]);
                acc[2][2] = fmaf(wv.z, iv.z, acc[2][2]);
                acc[2][3] = fmaf(wv.z, iv.w, acc[2][3]);
                acc[3][0] = fmaf(wv.w, iv.x, acc[3][0]);
                acc[3][1] = fmaf(wv.w, iv.y, acc[3][1]);
                acc[3][2] = fmaf(wv.w, iv.z, acc[3][2]);
                acc[3][3] = fmaf(wv.w, iv.w, acc[3][3]);
            }
            __syncthreads();
        }

        // ---- write k-split partials: part[kq][row][batch] ----
        #pragma unroll
        for (int ri = 0; ri < 4; ++ri) {
            float4 v = make_float4(acc[ri][0], acc[ri][1], acc[ri][2], acc[ri][3]);
            *(float4*)(part + ((kq * NROWS) + (r4 << 2) + ri) * NBATCH + (b4 << 2)) = v;
        }
        __syncthreads();

        // ---- elementwise LSTM cell: thread (eb, ejj) ----
        {
            float gv[4];
            #pragma unroll
            for (int gt = 0; gt < 4; ++gt) {
                int row = gt * 4 + ejj;
                float v = bias[row];
                #pragma unroll
                for (int q = 0; q < 4; ++q)
                    v += part[(q * NROWS + row) * NBATCH + eb];
                gv[gt] = v;
            }
            float ig = 1.0f / (1.0f + __expf(-gv[0]));
            float fg = 1.0f / (1.0f + __expf(-gv[1]));
            float gg = tanhf(gv[2]);
            float og = 1.0f / (1.0f + __expf(-gv[3]));
            c_reg = fg * c_reg + ig * gg;
            float hv = og * tanhf(c_reg);

            size_t o = ((size_t)s * NBATCH + eb) * HID + bk * HPB + ejj;
            h_out[o] = hv;
            c_out[o] = c_reg;
        }

        // ---- grid barrier: h[s] visible everywhere before step s+1 ----
        __syncthreads();
        if (t == 0) {
            __threadfence();
            unsigned target = (unsigned)(NBLK) * (unsigned)(s + 1);
            atomicAdd(&g_bar, 1u);
            while (*((volatile unsigned int*)&g_bar) < target) { }
            __threadfence();
        }
        __syncthreads();
    }
}

extern "C" void kernel_launch(void* const* d_in, const int* in_sizes, int n_in,
                              void* d_out, int out_size)
{
    (void)in_sizes; (void)n_in; (void)out_size;
    const float* x   = (const float*)d_in[0];
    const float* Wih = (const float*)d_in[1];
    const float* Whh = (const float*)d_in[2];
    const float* bih = (const float*)d_in[3];
    const float* bhh = (const float*)d_in[4];
    float* out = (float*)d_out;

    static int smem_set = 0;
    if (!smem_set) {
        cudaFuncSetAttribute(lstm_persistent_kernel,
                             cudaFuncAttributeMaxDynamicSharedMemorySize,
                             SMEM_BYTES);
        smem_set = 1;
    }

    reset_bar_kernel<<<1, 1>>>();
    lstm_persistent_kernel<<<NBLK, NTHR, SMEM_BYTES>>>(x, Wih, Whh, bih, bhh, out);
}